// round 14
// baseline (speedup 1.0000x reference)
#include <cuda_runtime.h>

// ADDLoss — prep (AoS->SoA quads) + main.
// R13 diagnosis: AoS point loads put lanes at 48B stride -> each LDG.128
// touches ~12 cache lines; 36 L1 wavefronts per quad-pair vs 12 minimal.
// L1-wavefront time (~15.8K cyc/SM) exceeded the fma floor (~11K) — memory
// layout, not math, was binding. SoA quad arrays make every point-load
// lane-contiguous (16B stride): 3x fewer wavefronts.
// Main: 16 lanes/element, 2 elements/warp, 8192 warps, prefetch pipeline,
// scalar Horner quadratic form, sqrt.approx(|x|), fixed-point int reduce.

#define BATCH      16384
#define NPTS       500
#define NQUADS     125                   // 4 points per quad
#define NOBJ       30
#define OBJ_QSTRIDE 128                  // padded quads per object
#define WARPS_PB   4
#define THREADS_PB (WARPS_PB * 32)       // 128
#define ELEMS_PW   2                     // elements per warp (16 lanes each)
#define NBLOCKS    (BATCH / (WARPS_PB * ELEMS_PW))   // 2048

#define FP_SCALE     68719476736.0       // 2^36
#define INV_FP_SCALE (1.0 / 68719476736.0)

typedef unsigned long long u64;

__device__ float4 g_x4[NOBJ * OBJ_QSTRIDE];   // x of points 4q..4q+3
__device__ float4 g_y4[NOBJ * OBJ_QSTRIDE];
__device__ float4 g_z4[NOBJ * OBJ_QSTRIDE];
__device__ u64 g_sum;                    // zero-init; self-resets each launch
__device__ unsigned int g_count;

__device__ __forceinline__ float sqrt_abs(float x) {
    float r; asm("sqrt.approx.f32 %0, %1;" : "=f"(r) : "f"(fabsf(x))); return r;
}

// ---- prep: AoS points -> SoA quad components -------------------------------
__global__ __launch_bounds__(128)
void addloss_prep(const float* __restrict__ points)
{
    const int o = blockIdx.x;
    const int j = threadIdx.x;           // quad index
    if (j >= NQUADS) return;
    const float4* src = reinterpret_cast<const float4*>(points + (size_t)o * (NPTS * 3));
    const float4 a = src[3*j + 0];       // p0.xyz, p1.x
    const float4 b = src[3*j + 1];       // p1.yz, p2.xy
    const float4 c = src[3*j + 2];       // p2.z, p3.xyz
    g_x4[o * OBJ_QSTRIDE + j] = make_float4(a.x, a.w, b.z, c.y);
    g_y4[o * OBJ_QSTRIDE + j] = make_float4(a.y, b.x, b.w, c.z);
    g_z4[o * OBJ_QSTRIDE + j] = make_float4(a.z, b.y, c.x, c.w);
}

// ---- main ------------------------------------------------------------------
__global__ __launch_bounds__(THREADS_PB)
void addloss_kernel(const float* __restrict__ pred_r,
                    const float* __restrict__ pred_t,
                    const float* __restrict__ gt_r,
                    const float* __restrict__ gt_t,
                    const int*   __restrict__ obj_ids,
                    float*       __restrict__ out)
{
    const int warp_in_blk = threadIdx.x >> 5;
    const int lane        = threadIdx.x & 31;
    const int l16         = lane & 15;
    const int half        = lane >> 4;
    const int b = (blockIdx.x * WARPS_PB + warp_in_blk) * ELEMS_PW + half;

    __shared__ float sh_val[WARPS_PB];

    // ---- per-element prologue (lane-replicated; issue cost once per warp) ----
    int oid = obj_ids[b];
    oid = min(max(oid, 0), NOBJ - 1);
    const int qbase = oid * OBJ_QSTRIDE;

    const float4 qp = reinterpret_cast<const float4*>(pred_r)[b];
    const float4 qg = reinterpret_cast<const float4*>(gt_r)[b];
    const float pw = qp.x, px_ = qp.y, py_ = qp.z, pz_ = qp.w;
    const float gw = qg.x, gx_ = qg.y, gy_ = qg.z, gz_ = qg.w;

    const float m00 = -2.f*(py_*py_ + pz_*pz_ - gy_*gy_ - gz_*gz_);
    const float m01 =  2.f*(px_*py_ - pw*pz_ - gx_*gy_ + gw*gz_);
    const float m02 =  2.f*(px_*pz_ + pw*py_ - gx_*gz_ - gw*gy_);
    const float m10 =  2.f*(px_*py_ + pw*pz_ - gx_*gy_ - gw*gz_);
    const float m11 = -2.f*(px_*px_ + pz_*pz_ - gx_*gx_ - gz_*gz_);
    const float m12 =  2.f*(py_*pz_ - pw*px_ - gy_*gz_ + gw*gx_);
    const float m20 =  2.f*(px_*pz_ - pw*py_ - gx_*gz_ + gw*gy_);
    const float m21 =  2.f*(py_*pz_ + pw*px_ - gy_*gz_ - gw*gx_);
    const float m22 = -2.f*(px_*px_ + py_*py_ - gx_*gx_ - gy_*gy_);

    const float tx = pred_t[3*b+0] - gt_t[3*b+0];
    const float ty = pred_t[3*b+1] - gt_t[3*b+1];
    const float tz = pred_t[3*b+2] - gt_t[3*b+2];
    const float t2 = tx*tx + ty*ty + tz*tz;

    const float s00 = m00*m00 + m10*m10 + m20*m20;
    const float s11 = m01*m01 + m11*m11 + m21*m21;
    const float s22 = m02*m02 + m12*m12 + m22*m22;
    const float s01 = 2.f*(m00*m01 + m10*m11 + m20*m21);
    const float s02 = 2.f*(m00*m02 + m10*m12 + m20*m22);
    const float s12 = 2.f*(m01*m02 + m11*m12 + m21*m22);
    const float c0  = 2.f*(m00*tx + m10*ty + m20*tz);
    const float c1  = 2.f*(m01*tx + m11*ty + m21*tz);
    const float c2  = 2.f*(m02*tx + m12*ty + m22*tz);

    float acc0 = 0.f, acc1 = 0.f;

    #define POINT_TERM(PX, PY, PZ, ACC) do {                                   \
        const float _px = (PX), _py = (PY), _pz = (PZ);                        \
        const float _U  = fmaf(s02, _pz, fmaf(s01, _py, s00*_px));             \
        const float _V  = fmaf(s12, _pz, s11*_py);                             \
        const float _W  = s22*_pz;                                             \
        const float _a2 = fmaf(_pz, _W, fmaf(_py, _V, _px*_U));                \
        const float _ln = fmaf(c0, _px, fmaf(c1, _py, fmaf(c2, _pz, t2)));     \
        const float _b2 = _a2 + _ln;                                           \
        ACC += sqrt_abs(_a2) + sqrt_abs(_b2);                                  \
    } while (0)

    // SoA quad: X,Y,Z each hold one component of 4 points
    #define COMPUTE_QUAD(X, Y, Z) do {                                         \
        POINT_TERM((X).x, (Y).x, (Z).x, acc0);                                 \
        POINT_TERM((X).y, (Y).y, (Z).y, acc1);                                 \
        POINT_TERM((X).z, (Y).z, (Z).z, acc0);                                 \
        POINT_TERM((X).w, (Y).w, (Z).w, acc1);                                 \
    } while (0)

    // ---- pipelined loop: 7 strided quads + tail quad (l16 < 13) ----
    const bool has_tail = (l16 < NQUADS - 112);   // l16 < 13
    const int  tail_q   = qbase + 112 + l16;

    float4 vx = g_x4[qbase + l16], vy = g_y4[qbase + l16], vz = g_z4[qbase + l16];

    #pragma unroll
    for (int k = 0; k < 7; ++k) {
        float4 nx, ny, nz;
        if (k < 6) {
            const int q = qbase + l16 + 16*(k+1);
            nx = g_x4[q]; ny = g_y4[q]; nz = g_z4[q];
        } else if (has_tail) {
            nx = g_x4[tail_q]; ny = g_y4[tail_q]; nz = g_z4[tail_q];
        }
        COMPUTE_QUAD(vx, vy, vz);
        vx = nx; vy = ny; vz = nz;
    }
    if (has_tail)
        COMPUTE_QUAD(vx, vy, vz);

    #undef COMPUTE_QUAD
    #undef POINT_TERM

    // ---- 16-lane segment reduce (fixed order -> deterministic) ----
    float s = acc0 + acc1;
    s += __shfl_down_sync(0xffffffffu, s, 8, 16);
    s += __shfl_down_sync(0xffffffffu, s, 4, 16);
    s += __shfl_down_sync(0xffffffffu, s, 2, 16);
    s += __shfl_down_sync(0xffffffffu, s, 1, 16);

    const float s_elem = fmaf(s, 1.0f / NPTS, sqrt_abs(t2));
    const float e1 = __shfl_sync(0xffffffffu, s_elem, 16);

    if (lane == 0)
        sh_val[warp_in_blk] = s_elem + e1;
    __syncthreads();

    if (threadIdx.x == 0) {
        float blk = 0.f;
        #pragma unroll
        for (int w = 0; w < WARPS_PB; w++) blk += sh_val[w];

        const u64 q = (u64)__double2ll_rn((double)blk * FP_SCALE);
        atomicAdd(&g_sum, q);
        __threadfence();
        const unsigned int ticket = atomicAdd(&g_count, 1u);
        if (ticket == NBLOCKS - 1) {
            const u64 total = atomicExch(&g_sum, 0ULL);  // read + reset for replay
            g_count = 0u;
            out[0] = (float)((double)total * INV_FP_SCALE * (1.0 / BATCH));
        }
    }
}

extern "C" void kernel_launch(void* const* d_in, const int* in_sizes, int n_in,
                              void* d_out, int out_size)
{
    const float* pred_r  = (const float*)d_in[0];
    const float* pred_t  = (const float*)d_in[1];
    const float* gt_r    = (const float*)d_in[2];
    const float* gt_t    = (const float*)d_in[3];
    const int*   obj_ids = (const int*)  d_in[4];
    const float* points  = (const float*)d_in[5];
    float* out = (float*)d_out;

    addloss_prep<<<NOBJ, 128>>>(points);
    addloss_kernel<<<NBLOCKS, THREADS_PB>>>(pred_r, pred_t, gt_r, gt_t,
                                            obj_ids, out);
}

// round 15
// speedup vs baseline: 1.0152x; 1.0152x over previous
#include <cuda_runtime.h>
#include <cuda_fp16.h>

// ADDLoss — fp16x2 packed math (2 points per HFMA2) + MUFU sqrt via bit-trick.
// R11-R14 model: stream was ~83% fma-pipe (rt_SMSP=2) -> issue capped ~60%,
// runtime = 30 fma-cyc/point. HFMA2/HMUL2/HADD2 are full-rate (rt=2) on the
// same pipe but do 2 points/op -> fma cost halves. fp16->fp32 for sqrt WITHOUT
// cvt (XU pipe): (h&0x7FFF)<<13 as f32 == x*2^-112; sqrt.approx gives
// sqrt(x)*2^-56; accumulate with FFMA-imm (rt=1) * 2^56. New floor = MUFU.
// prep: points -> fp16x2 SoA groups of 8 pts, padded 500->512 (pad = zero
// points; each contributes exactly sqrt(t2h) via B2=T2h -> subtracted exactly).
// main: 1024x128, 4 elems/warp, 8 lanes/elem (R12 best config), uniform
// 8 groups/lane (no tail branch), prefetch pipeline, fixed-point int reduce.

#define BATCH      16384
#define NPTS       500
#define NOBJ       30
#define NGROUPS    64                    // 8 points per group; 512 padded points
#define WARPS_PB   4
#define THREADS_PB (WARPS_PB * 32)       // 128
#define ELEMS_PW   4                     // elements per warp (8 lanes each)
#define NBLOCKS    (BATCH / (WARPS_PB * ELEMS_PW))   // 1024
#define PREP_THREADS 256
#define PREP_BLOCKS  ((NOBJ * NGROUPS + PREP_THREADS - 1) / PREP_THREADS)  // 8

#define FP_SCALE     68719476736.0       // 2^36
#define INV_FP_SCALE (1.0 / 68719476736.0)

typedef unsigned long long u64;
typedef unsigned int u32;

__device__ uint4 g_hx[NOBJ * NGROUPS];   // 4x half2 = x of points 8g..8g+7
__device__ uint4 g_hy[NOBJ * NGROUPS];
__device__ uint4 g_hz[NOBJ * NGROUPS];
__device__ u64 g_sum;                    // zero-init; self-resets each launch
__device__ u32 g_count;

__device__ __forceinline__ __half2 u2h(u32 u) { __half2 h; memcpy(&h, &u, 4); return h; }
__device__ __forceinline__ u32 h2u(__half2 h) { u32 u; memcpy(&u, &h, 4); return u; }

__device__ __forceinline__ float sqrt_abs(float x) {
    float r; asm("sqrt.approx.f32 %0, %1;" : "=f"(r) : "f"(fabsf(x))); return r;
}
// u = (h&0x7FFF)<<13 reinterpreted: value = x * 2^-112 -> returns sqrt(x)*2^-56
__device__ __forceinline__ float sqrt_scaled(u32 u) {
    float r; asm("sqrt.approx.f32 %0, %1;" : "=f"(r) : "f"(__uint_as_float(u)));
    return r;
}

// ---- prep: AoS fp32 points -> fp16x2 SoA groups (zero-padded to 512) -------
__global__ __launch_bounds__(PREP_THREADS)
void addloss_prep(const float* __restrict__ points)
{
    const int idx = blockIdx.x * PREP_THREADS + threadIdx.x;
    if (idx >= NOBJ * NGROUPS) return;
    const int o = idx / NGROUPS, g = idx % NGROUPS;
    const float* base = points + (size_t)o * (NPTS * 3);
    float x[8], y[8], z[8];
    #pragma unroll
    for (int i = 0; i < 8; i++) {
        const int n = g * 8 + i;
        if (n < NPTS) { x[i] = base[3*n]; y[i] = base[3*n+1]; z[i] = base[3*n+2]; }
        else          { x[i] = 0.f; y[i] = 0.f; z[i] = 0.f; }
    }
    g_hx[idx] = make_uint4(h2u(__floats2half2_rn(x[0], x[1])), h2u(__floats2half2_rn(x[2], x[3])),
                           h2u(__floats2half2_rn(x[4], x[5])), h2u(__floats2half2_rn(x[6], x[7])));
    g_hy[idx] = make_uint4(h2u(__floats2half2_rn(y[0], y[1])), h2u(__floats2half2_rn(y[2], y[3])),
                           h2u(__floats2half2_rn(y[4], y[5])), h2u(__floats2half2_rn(y[6], y[7])));
    g_hz[idx] = make_uint4(h2u(__floats2half2_rn(z[0], z[1])), h2u(__floats2half2_rn(z[2], z[3])),
                           h2u(__floats2half2_rn(z[4], z[5])), h2u(__floats2half2_rn(z[6], z[7])));
}

// ---- main ------------------------------------------------------------------
__global__ __launch_bounds__(THREADS_PB)
void addloss_kernel(const float* __restrict__ pred_r,
                    const float* __restrict__ pred_t,
                    const float* __restrict__ gt_r,
                    const float* __restrict__ gt_t,
                    const int*   __restrict__ obj_ids,
                    float*       __restrict__ out)
{
    const int warp_in_blk = threadIdx.x >> 5;
    const int lane        = threadIdx.x & 31;
    const int l8          = lane & 7;
    const int quarter     = lane >> 3;
    const int b = (blockIdx.x * WARPS_PB + warp_in_blk) * ELEMS_PW + quarter;

    __shared__ float sh_val[WARPS_PB];

    // ---- per-element prologue, fp32 (lane-replicated; issued once/warp) ----
    int oid = obj_ids[b];
    oid = min(max(oid, 0), NOBJ - 1);
    const int gbase = oid * NGROUPS + l8;

    const float4 qp = reinterpret_cast<const float4*>(pred_r)[b];
    const float4 qg = reinterpret_cast<const float4*>(gt_r)[b];
    const float pw = qp.x, px_ = qp.y, py_ = qp.z, pz_ = qp.w;
    const float gw = qg.x, gx_ = qg.y, gy_ = qg.z, gz_ = qg.w;

    const float m00 = -2.f*(py_*py_ + pz_*pz_ - gy_*gy_ - gz_*gz_);
    const float m01 =  2.f*(px_*py_ - pw*pz_ - gx_*gy_ + gw*gz_);
    const float m02 =  2.f*(px_*pz_ + pw*py_ - gx_*gz_ - gw*gy_);
    const float m10 =  2.f*(px_*py_ + pw*pz_ - gx_*gy_ - gw*gz_);
    const float m11 = -2.f*(px_*px_ + pz_*pz_ - gx_*gx_ - gz_*gz_);
    const float m12 =  2.f*(py_*pz_ - pw*px_ - gy_*gz_ + gw*gx_);
    const float m20 =  2.f*(px_*pz_ - pw*py_ - gx_*gz_ + gw*gy_);
    const float m21 =  2.f*(py_*pz_ + pw*px_ - gy_*gz_ - gw*gx_);
    const float m22 = -2.f*(px_*px_ + py_*py_ - gx_*gx_ - gy_*gy_);

    const float tx = pred_t[3*b+0] - gt_t[3*b+0];
    const float ty = pred_t[3*b+1] - gt_t[3*b+1];
    const float tz = pred_t[3*b+2] - gt_t[3*b+2];
    const float t2 = tx*tx + ty*ty + tz*tz;

    const float s00 = m00*m00 + m10*m10 + m20*m20;
    const float s11 = m01*m01 + m11*m11 + m21*m21;
    const float s22 = m02*m02 + m12*m12 + m22*m22;
    const float s01 = 2.f*(m00*m01 + m10*m11 + m20*m21);
    const float s02 = 2.f*(m00*m02 + m10*m12 + m20*m22);
    const float s12 = 2.f*(m01*m02 + m11*m12 + m21*m22);
    const float c0  = 2.f*(m00*tx + m10*ty + m20*tz);
    const float c1  = 2.f*(m01*tx + m11*ty + m21*tz);
    const float c2  = 2.f*(m02*tx + m12*ty + m22*tz);

    // packed fp16 coefficients (same value both halves)
    const __half2 HS00 = __float2half2_rn(s00), HS11 = __float2half2_rn(s11);
    const __half2 HS22 = __float2half2_rn(s22), HS01 = __float2half2_rn(s01);
    const __half2 HS02 = __float2half2_rn(s02), HS12 = __float2half2_rn(s12);
    const __half2 HC0  = __float2half2_rn(c0),  HC1  = __float2half2_rn(c1);
    const __half2 HC2  = __float2half2_rn(c2),  HT2  = __float2half2_rn(t2);

    float acc0 = 0.f, acc1 = 0.f;

    // one pair = 2 points: 13 half2 fma-pipe ops, 8 alu extracts,
    // 4 MUFU sqrt, 4 FFMA-imm accumulates.
    #define PAIR(PXb, PYb, PZb) do {                                           \
        const __half2 hx = u2h(PXb), hy = u2h(PYb), hz = u2h(PZb);             \
        const __half2 U  = __hfma2(HS02, hz, __hfma2(HS01, hy, __hmul2(HS00, hx))); \
        const __half2 V  = __hfma2(HS12, hz, __hmul2(HS11, hy));               \
        const __half2 W  = __hmul2(HS22, hz);                                  \
        const __half2 A2 = __hfma2(hz, W, __hfma2(hy, V, __hmul2(hx, U)));     \
        const __half2 LN = __hfma2(HC0, hx, __hfma2(HC1, hy, __hfma2(HC2, hz, HT2))); \
        const __half2 B2 = __hadd2(A2, LN);                                    \
        const u32 ua = h2u(A2), ub = h2u(B2);                                  \
        acc0 = fmaf(sqrt_scaled((ua & 0x7FFFu) << 13), 0x1p56f, acc0);         \
        acc1 = fmaf(sqrt_scaled((ua >> 3) & 0x0FFFE000u), 0x1p56f, acc1);      \
        acc0 = fmaf(sqrt_scaled((ub & 0x7FFFu) << 13), 0x1p56f, acc0);         \
        acc1 = fmaf(sqrt_scaled((ub >> 3) & 0x0FFFE000u), 0x1p56f, acc1);      \
    } while (0)

    #define GROUP(X, Y, Z) do {                                                \
        PAIR((X).x, (Y).x, (Z).x);                                             \
        PAIR((X).y, (Y).y, (Z).y);                                             \
        PAIR((X).z, (Y).z, (Z).z);                                             \
        PAIR((X).w, (Y).w, (Z).w);                                             \
    } while (0)

    // ---- uniform pipelined loop: 8 groups per lane, no tail branch ----
    uint4 X = g_hx[gbase], Y = g_hy[gbase], Z = g_hz[gbase];
    #pragma unroll
    for (int k = 0; k < 8; ++k) {
        uint4 nX, nY, nZ;
        if (k < 7) {
            const int q = gbase + 8 * (k + 1);
            nX = g_hx[q]; nY = g_hy[q]; nZ = g_hz[q];
        }
        GROUP(X, Y, Z);
        X = nX; Y = nY; Z = nZ;
    }
    #undef GROUP
    #undef PAIR

    // ---- 8-lane segment reduce (fixed order -> deterministic) ----
    float s = acc0 + acc1;
    s += __shfl_down_sync(0xffffffffu, s, 4, 8);
    s += __shfl_down_sync(0xffffffffu, s, 2, 8);
    s += __shfl_down_sync(0xffffffffu, s, 1, 8);

    // pad correction: 12 pad points each contributed exactly sqrt-chain(T2h)
    const u32  t2b  = h2u(HT2) & 0xFFFFu;
    const float corr = sqrt_scaled((t2b & 0x7FFFu) << 13) * 0x1p56f;
    const float s_elem = fmaf(s - 12.f * corr, 1.0f / NPTS, sqrt_abs(t2));

    // combine the 4 element totals of this warp (fixed order)
    const float e1 = __shfl_sync(0xffffffffu, s_elem, 8);
    const float e2 = __shfl_sync(0xffffffffu, s_elem, 16);
    const float e3 = __shfl_sync(0xffffffffu, s_elem, 24);

    if (lane == 0)
        sh_val[warp_in_blk] = (s_elem + e1) + (e2 + e3);
    __syncthreads();

    if (threadIdx.x == 0) {
        float blk = 0.f;
        #pragma unroll
        for (int w = 0; w < WARPS_PB; w++) blk += sh_val[w];

        const u64 q = (u64)__double2ll_rn((double)blk * FP_SCALE);
        atomicAdd(&g_sum, q);
        __threadfence();
        const u32 ticket = atomicAdd(&g_count, 1u);
        if (ticket == NBLOCKS - 1) {
            const u64 total = atomicExch(&g_sum, 0ULL);  // read + reset for replay
            g_count = 0u;
            out[0] = (float)((double)total * INV_FP_SCALE * (1.0 / BATCH));
        }
    }
}

extern "C" void kernel_launch(void* const* d_in, const int* in_sizes, int n_in,
                              void* d_out, int out_size)
{
    const float* pred_r  = (const float*)d_in[0];
    const float* pred_t  = (const float*)d_in[1];
    const float* gt_r    = (const float*)d_in[2];
    const float* gt_t    = (const float*)d_in[3];
    const int*   obj_ids = (const int*)  d_in[4];
    const float* points  = (const float*)d_in[5];
    float* out = (float*)d_out;

    addloss_prep<<<PREP_BLOCKS, PREP_THREADS>>>(points);
    addloss_kernel<<<NBLOCKS, THREADS_PB>>>(pred_r, pred_t, gt_r, gt_t,
                                            obj_ids, out);
}

// round 16
// speedup vs baseline: 1.0635x; 1.0476x over previous
#include <cuda_runtime.h>
#include <cuda_fp16.h>

// ADDLoss — fp16x2 packed math, R15 + occupancy & prep fixes.
// R15 win: HFMA2 halves fma-pipe work; sqrt via bit-trick (no cvt): half-bits
// (h&0x7FFF)<<13 as f32 = x*2^-112, sqrt.approx -> sqrt(x)*2^-56, FFMA-imm
// accumulate *2^56. R15 miss: main occ 34.5% (1024 blocks) + uncoalesced prep
// gather (~4.5us overhead). R16: 16 lanes/elem -> 2048 blocks / 8192 warps
// (55 warps/SM), EXACTLY 4 groups/lane (no tail); prep stages fp32 via smem
// with coalesced loads. Deterministic fixed-point integer reduce.

#define BATCH      16384
#define NPTS       500
#define NOBJ       30
#define NGROUPS    64                    // 8 points/group; 512 padded points
#define WARPS_PB   4
#define THREADS_PB (WARPS_PB * 32)       // 128
#define ELEMS_PW   2                     // elements per warp (16 lanes each)
#define NBLOCKS    (BATCH / (WARPS_PB * ELEMS_PW))   // 2048

#define FP_SCALE     68719476736.0       // 2^36
#define INV_FP_SCALE (1.0 / 68719476736.0)

typedef unsigned long long u64;
typedef unsigned int u32;

__device__ uint4 g_hx[NOBJ * NGROUPS];   // 4x half2 = x of points 8g..8g+7
__device__ uint4 g_hy[NOBJ * NGROUPS];
__device__ uint4 g_hz[NOBJ * NGROUPS];
__device__ u64 g_sum;                    // zero-init; self-resets each launch
__device__ u32 g_count;

__device__ __forceinline__ __half2 u2h(u32 u) { __half2 h; memcpy(&h, &u, 4); return h; }
__device__ __forceinline__ u32 h2u(__half2 h) { u32 u; memcpy(&u, &h, 4); return u; }

__device__ __forceinline__ float sqrt_abs(float x) {
    float r; asm("sqrt.approx.f32 %0, %1;" : "=f"(r) : "f"(fabsf(x))); return r;
}
// u holds x*2^-112 as f32 bits -> returns sqrt(x)*2^-56
__device__ __forceinline__ float sqrt_scaled(u32 u) {
    float r; asm("sqrt.approx.f32 %0, %1;" : "=f"(r) : "f"(__uint_as_float(u)));
    return r;
}

// ---- prep: coalesced fp32 stage -> fp16x2 SoA groups (padded to 512 pts) ----
__global__ __launch_bounds__(128)
void addloss_prep(const float* __restrict__ points)
{
    __shared__ float sp[1536];           // 512 padded points x 3 comps (AoS)
    const int o   = blockIdx.x;
    const int tid = threadIdx.x;

    // coalesced load of this object's 1500 floats (+ zero pad to 1536)
    const float* src = points + (size_t)o * (NPTS * 3);
    #pragma unroll
    for (int i = tid; i < 1536; i += 128)
        sp[i] = (i < NPTS * 3) ? src[i] : 0.f;
    __syncthreads();

    // threads 0..63: build one 8-point group each
    if (tid < NGROUPS) {
        float x[8], y[8], z[8];
        #pragma unroll
        for (int i = 0; i < 8; i++) {
            const int n = tid * 8 + i;
            x[i] = sp[3*n]; y[i] = sp[3*n+1]; z[i] = sp[3*n+2];
        }
        const int idx = o * NGROUPS + tid;
        g_hx[idx] = make_uint4(h2u(__floats2half2_rn(x[0],x[1])), h2u(__floats2half2_rn(x[2],x[3])),
                               h2u(__floats2half2_rn(x[4],x[5])), h2u(__floats2half2_rn(x[6],x[7])));
        g_hy[idx] = make_uint4(h2u(__floats2half2_rn(y[0],y[1])), h2u(__floats2half2_rn(y[2],y[3])),
                               h2u(__floats2half2_rn(y[4],y[5])), h2u(__floats2half2_rn(y[6],y[7])));
        g_hz[idx] = make_uint4(h2u(__floats2half2_rn(z[0],z[1])), h2u(__floats2half2_rn(z[2],z[3])),
                               h2u(__floats2half2_rn(z[4],z[5])), h2u(__floats2half2_rn(z[6],z[7])));
    }
}

// ---- main ------------------------------------------------------------------
__global__ __launch_bounds__(THREADS_PB)
void addloss_kernel(const float* __restrict__ pred_r,
                    const float* __restrict__ pred_t,
                    const float* __restrict__ gt_r,
                    const float* __restrict__ gt_t,
                    const int*   __restrict__ obj_ids,
                    float*       __restrict__ out)
{
    const int warp_in_blk = threadIdx.x >> 5;
    const int lane        = threadIdx.x & 31;
    const int l16         = lane & 15;
    const int half        = lane >> 4;
    const int b = (blockIdx.x * WARPS_PB + warp_in_blk) * ELEMS_PW + half;

    __shared__ float sh_val[WARPS_PB];

    // ---- per-element prologue, fp32 (lane-replicated; issued once/warp) ----
    int oid = obj_ids[b];
    oid = min(max(oid, 0), NOBJ - 1);
    const int gbase = oid * NGROUPS + l16;

    const float4 qp = reinterpret_cast<const float4*>(pred_r)[b];
    const float4 qg = reinterpret_cast<const float4*>(gt_r)[b];
    const float pw = qp.x, px_ = qp.y, py_ = qp.z, pz_ = qp.w;
    const float gw = qg.x, gx_ = qg.y, gy_ = qg.z, gz_ = qg.w;

    const float m00 = -2.f*(py_*py_ + pz_*pz_ - gy_*gy_ - gz_*gz_);
    const float m01 =  2.f*(px_*py_ - pw*pz_ - gx_*gy_ + gw*gz_);
    const float m02 =  2.f*(px_*pz_ + pw*py_ - gx_*gz_ - gw*gy_);
    const float m10 =  2.f*(px_*py_ + pw*pz_ - gx_*gy_ - gw*gz_);
    const float m11 = -2.f*(px_*px_ + pz_*pz_ - gx_*gx_ - gz_*gz_);
    const float m12 =  2.f*(py_*pz_ - pw*px_ - gy_*gz_ + gw*gx_);
    const float m20 =  2.f*(px_*pz_ - pw*py_ - gx_*gz_ + gw*gy_);
    const float m21 =  2.f*(py_*pz_ + pw*px_ - gy_*gz_ - gw*gx_);
    const float m22 = -2.f*(px_*px_ + py_*py_ - gx_*gx_ - gy_*gy_);

    const float tx = pred_t[3*b+0] - gt_t[3*b+0];
    const float ty = pred_t[3*b+1] - gt_t[3*b+1];
    const float tz = pred_t[3*b+2] - gt_t[3*b+2];
    const float t2 = tx*tx + ty*ty + tz*tz;

    const float s00 = m00*m00 + m10*m10 + m20*m20;
    const float s11 = m01*m01 + m11*m11 + m21*m21;
    const float s22 = m02*m02 + m12*m12 + m22*m22;
    const float s01 = 2.f*(m00*m01 + m10*m11 + m20*m21);
    const float s02 = 2.f*(m00*m02 + m10*m12 + m20*m22);
    const float s12 = 2.f*(m01*m02 + m11*m12 + m21*m22);
    const float c0  = 2.f*(m00*tx + m10*ty + m20*tz);
    const float c1  = 2.f*(m01*tx + m11*ty + m21*tz);
    const float c2  = 2.f*(m02*tx + m12*ty + m22*tz);

    const __half2 HS00 = __float2half2_rn(s00), HS11 = __float2half2_rn(s11);
    const __half2 HS22 = __float2half2_rn(s22), HS01 = __float2half2_rn(s01);
    const __half2 HS02 = __float2half2_rn(s02), HS12 = __float2half2_rn(s12);
    const __half2 HC0  = __float2half2_rn(c0),  HC1  = __float2half2_rn(c1);
    const __half2 HC2  = __float2half2_rn(c2),  HT2  = __float2half2_rn(t2);

    float acc0 = 0.f, acc1 = 0.f;

    // one pair = 2 points: 13 half2 fma-pipe ops, 8 alu extracts,
    // 4 MUFU sqrt, 4 FFMA-imm accumulates.
    #define PAIR(PXb, PYb, PZb) do {                                           \
        const __half2 hx = u2h(PXb), hy = u2h(PYb), hz = u2h(PZb);             \
        const __half2 U  = __hfma2(HS02, hz, __hfma2(HS01, hy, __hmul2(HS00, hx))); \
        const __half2 V  = __hfma2(HS12, hz, __hmul2(HS11, hy));               \
        const __half2 W  = __hmul2(HS22, hz);                                  \
        const __half2 A2 = __hfma2(hz, W, __hfma2(hy, V, __hmul2(hx, U)));     \
        const __half2 LN = __hfma2(HC0, hx, __hfma2(HC1, hy, __hfma2(HC2, hz, HT2))); \
        const __half2 B2 = __hadd2(A2, LN);                                    \
        const u32 ua = h2u(A2), ub = h2u(B2);                                  \
        acc0 = fmaf(sqrt_scaled((ua & 0x7FFFu) << 13), 0x1p56f, acc0);         \
        acc1 = fmaf(sqrt_scaled((ua >> 3) & 0x0FFFE000u), 0x1p56f, acc1);      \
        acc0 = fmaf(sqrt_scaled((ub & 0x7FFFu) << 13), 0x1p56f, acc0);         \
        acc1 = fmaf(sqrt_scaled((ub >> 3) & 0x0FFFE000u), 0x1p56f, acc1);      \
    } while (0)

    #define GROUP(X, Y, Z) do {                                                \
        PAIR((X).x, (Y).x, (Z).x);                                             \
        PAIR((X).y, (Y).y, (Z).y);                                             \
        PAIR((X).z, (Y).z, (Z).z);                                             \
        PAIR((X).w, (Y).w, (Z).w);                                             \
    } while (0)

    // ---- uniform pipelined loop: exactly 4 groups per lane (64 = 16*4) ----
    uint4 X = g_hx[gbase], Y = g_hy[gbase], Z = g_hz[gbase];
    #pragma unroll
    for (int k = 0; k < 4; ++k) {
        uint4 nX, nY, nZ;
        if (k < 3) {
            const int q = gbase + 16 * (k + 1);
            nX = g_hx[q]; nY = g_hy[q]; nZ = g_hz[q];
        }
        GROUP(X, Y, Z);
        X = nX; Y = nY; Z = nZ;
    }
    #undef GROUP
    #undef PAIR

    // ---- 16-lane segment reduce (fixed order -> deterministic) ----
    float s = acc0 + acc1;
    s += __shfl_down_sync(0xffffffffu, s, 8, 16);
    s += __shfl_down_sync(0xffffffffu, s, 4, 16);
    s += __shfl_down_sync(0xffffffffu, s, 2, 16);
    s += __shfl_down_sync(0xffffffffu, s, 1, 16);

    // pad correction: 12 pad (zero) points each contributed sqrt-chain(T2h)
    const u32  t2b  = h2u(HT2) & 0xFFFFu;
    const float corr = sqrt_scaled((t2b & 0x7FFFu) << 13) * 0x1p56f;
    const float s_elem = fmaf(s - 12.f * corr, 1.0f / NPTS, sqrt_abs(t2));

    const float e1 = __shfl_sync(0xffffffffu, s_elem, 16);

    if (lane == 0)
        sh_val[warp_in_blk] = s_elem + e1;
    __syncthreads();

    if (threadIdx.x == 0) {
        float blk = 0.f;
        #pragma unroll
        for (int w = 0; w < WARPS_PB; w++) blk += sh_val[w];

        const u64 q = (u64)__double2ll_rn((double)blk * FP_SCALE);
        atomicAdd(&g_sum, q);
        __threadfence();
        const u32 ticket = atomicAdd(&g_count, 1u);
        if (ticket == NBLOCKS - 1) {
            const u64 total = atomicExch(&g_sum, 0ULL);  // read + reset for replay
            g_count = 0u;
            out[0] = (float)((double)total * INV_FP_SCALE * (1.0 / BATCH));
        }
    }
}

extern "C" void kernel_launch(void* const* d_in, const int* in_sizes, int n_in,
                              void* d_out, int out_size)
{
    const float* pred_r  = (const float*)d_in[0];
    const float* pred_t  = (const float*)d_in[1];
    const float* gt_r    = (const float*)d_in[2];
    const float* gt_t    = (const float*)d_in[3];
    const int*   obj_ids = (const int*)  d_in[4];
    const float* points  = (const float*)d_in[5];
    float* out = (float*)d_out;

    addloss_prep<<<NOBJ, 128>>>(points);
    addloss_kernel<<<NBLOCKS, THREADS_PB>>>(pred_r, pred_t, gt_r, gt_t,
                                            obj_ids, out);
}